// round 3
// baseline (speedup 1.0000x reference)
#include <cuda_runtime.h>
#include <cuda_bf16.h>
#include <cstdint>

// Problem constants
#define B_DIM 4
#define S_DIM 256
#define V_DIM 50257
#define D_DIM 768
#define ROWS (B_DIM * S_DIM)        // 1024
#define TOTAL_ELEMS ((long long)ROWS * V_DIM)   // 51,463,168  (divisible by 4)
#define N4 (TOTAL_ELEMS / 4)        // 12,865,792 float4 loads
#define D4 (D_DIM / 4)              // 192 float4 per output row

// Scratch: index and value of the single nonzero per (b,s) row.
__device__ int   g_idx[ROWS];
__device__ float g_val[ROWS];

// ---------------------------------------------------------------------------
// Kernel 1: scan the one_hot tensor as a flat float4 stream; on the rare
// nonzero, recover (row, col) and record it. Exactly one nonzero per row
// (per the reference's construction), so no atomics needed.
// ---------------------------------------------------------------------------
__global__ void __launch_bounds__(256)
scan_onehot_kernel(const float4* __restrict__ oh)
{
    unsigned int tid    = blockIdx.x * blockDim.x + threadIdx.x;
    unsigned int stride = gridDim.x * blockDim.x;

    #pragma unroll 4
    for (unsigned int i = tid; i < (unsigned int)N4; i += stride) {
        float4 v = oh[i];
        // fast path: all-zero (the overwhelmingly common case)
        if ((v.x != 0.0f) | (v.y != 0.0f) | (v.z != 0.0f) | (v.w != 0.0f)) {
            unsigned int base = i * 4u;
            float vals[4] = {v.x, v.y, v.z, v.w};
            #pragma unroll
            for (int k = 0; k < 4; ++k) {
                if (vals[k] != 0.0f) {
                    unsigned int flat = base + (unsigned int)k;
                    unsigned int row  = flat / (unsigned int)V_DIM;  // rare: cost ok
                    unsigned int col  = flat - row * (unsigned int)V_DIM;
                    g_idx[row] = (int)col;
                    g_val[row] = vals[k];
                }
            }
        }
    }
}

// ---------------------------------------------------------------------------
// Kernel 2: out[row][:] = g_val[row] * weight[g_idx[row]][:]
// 1024 blocks x 192 threads, one float4 per thread. Fully writes d_out.
// ---------------------------------------------------------------------------
__global__ void __launch_bounds__(D4)
gather_kernel(const float4* __restrict__ weight, float4* __restrict__ out)
{
    int row = blockIdx.x;
    int d   = threadIdx.x;          // 0..191

    int   idx = g_idx[row];         // broadcast load
    float s   = g_val[row];

    float4 w = weight[(size_t)idx * D4 + d];
    float4 o;
    o.x = s * w.x;
    o.y = s * w.y;
    o.z = s * w.z;
    o.w = s * w.w;
    out[(size_t)row * D4 + d] = o;
}

// ---------------------------------------------------------------------------
// Launch: inputs per metadata order: d_in[0] = one_hot [B,S,V] f32,
//         d_in[1] = weight [V,D] f32. Output [B,S,D] f32.
// ---------------------------------------------------------------------------
extern "C" void kernel_launch(void* const* d_in, const int* in_sizes, int n_in,
                              void* d_out, int out_size)
{
    const float4* oh     = (const float4*)d_in[0];
    const float4* weight = (const float4*)d_in[1];
    float4*       out    = (float4*)d_out;

    (void)in_sizes; (void)n_in; (void)out_size;

    // Scan: 2048 blocks x 256 threads -> each thread ~24 float4 iterations
    scan_onehot_kernel<<<2048, 256>>>(oh);
    // Gather: one block per output row
    gather_kernel<<<ROWS, D4>>>(weight, out);
}